// round 15
// baseline (speedup 1.0000x reference)
#include <cuda_runtime.h>
#include <cuda_fp16.h>
#include <cstdint>
#include <math.h>

#define B_ 4
#define L_ 4096
#define H_ 16
#define DH_ 128
#define DV_ 128
#define CHUNK_ 1024
#define NCHUNK_ 4
#define QT_ 64
#define KT_ 32
#define THREADS_ 128
/* (1/sqrt(128)) * log2(e) — folded into Q at prepass; exp(s*scale) == exp2(sacc) */
#define QSCALE_ 0.1275174290f

#define QTILE_BYTES 16384
#define KTILE_BYTES 8192
#define SMEM_BYTES (QTILE_BYTES + 6 * KTILE_BYTES) /* Q + 3 stages x (K,V) = 64KB */

// RoPE cos/sin table: [L_][64] of (cos, sin)
__device__ float2 g_rope[L_ * 64];

// Pre-transformed fp16 tensors, layout [b, l, h, d]
__device__ __half g_qh[B_ * L_ * H_ * DH_];
__device__ __half g_kh[B_ * L_ * H_ * DH_];
__device__ __half g_vh[B_ * L_ * H_ * DV_];

__global__ void rope_table_kernel() {
    int idx = blockIdx.x * blockDim.x + threadIdx.x;
    if (idx >= L_ * 64) return;
    int pos = idx >> 6;
    int j = idx & 63;
    const float coef = -0.14391156831212787f;  // -ln(10000)/64
    float freq = expf((float)j * coef);
    float ang = (float)pos * freq;  // fp32 rounding matches reference
    float s, c;
    sincosf(ang, &s, &c);
    g_rope[idx] = make_float2(c, s);
}

// RoPE + fp16 conversion pre-pass (Q additionally scaled by QSCALE_)
__global__ void prepass_kernel(const float* __restrict__ q,
                               const float* __restrict__ k,
                               const float* __restrict__ v) {
    int idx = blockIdx.x * blockDim.x + threadIdx.x;
    if (idx >= B_ * L_ * H_ * 64) return;
    int p = idx & 63;
    int rh = idx >> 6;              // (b*L + l)*H + h
    int gl = (rh >> 4) & (L_ - 1);  // l  (H_=16)
    size_t base = (size_t)rh * 128;
    float2 cs = g_rope[gl * 64 + p];

    float x1 = q[base + p], x2 = q[base + p + 64];
    g_qh[base + p]      = __float2half_rn((x1 * cs.x - x2 * cs.y) * QSCALE_);
    g_qh[base + p + 64] = __float2half_rn((x2 * cs.x + x1 * cs.y) * QSCALE_);

    x1 = k[base + p]; x2 = k[base + p + 64];
    g_kh[base + p]      = __float2half_rn(x1 * cs.x - x2 * cs.y);
    g_kh[base + p + 64] = __float2half_rn(x2 * cs.x + x1 * cs.y);

    g_vh[base + p]      = __float2half_rn(v[base + p]);
    g_vh[base + p + 64] = __float2half_rn(v[base + p + 64]);
}

__device__ __forceinline__ void ldm_x4(uint32_t r[4], uint32_t a) {
    asm volatile("ldmatrix.sync.aligned.m8n8.x4.shared.b16 {%0,%1,%2,%3}, [%4];\n"
                 : "=r"(r[0]), "=r"(r[1]), "=r"(r[2]), "=r"(r[3]) : "r"(a));
}
__device__ __forceinline__ void ldm_x4_t(uint32_t r[4], uint32_t a) {
    asm volatile("ldmatrix.sync.aligned.m8n8.x4.trans.shared.b16 {%0,%1,%2,%3}, [%4];\n"
                 : "=r"(r[0]), "=r"(r[1]), "=r"(r[2]), "=r"(r[3]) : "r"(a));
}
__device__ __forceinline__ void mma16816(float c[4], const uint32_t a[4],
                                         uint32_t b0, uint32_t b1) {
    asm volatile(
        "mma.sync.aligned.m16n8k16.row.col.f32.f16.f16.f32 "
        "{%0,%1,%2,%3}, {%4,%5,%6,%7}, {%8,%9}, {%0,%1,%2,%3};\n"
        : "+f"(c[0]), "+f"(c[1]), "+f"(c[2]), "+f"(c[3])
        : "r"(a[0]), "r"(a[1]), "r"(a[2]), "r"(a[3]), "r"(b0), "r"(b1));
}
__device__ __forceinline__ void cp16(uint32_t dst, const void* src) {
    asm volatile("cp.async.cg.shared.global [%0], [%1], 16;\n" ::"r"(dst), "l"(src));
}
__device__ __forceinline__ float ex2f(float x) {
    float y;
    asm("ex2.approx.f32 %0, %1;" : "=f"(y) : "f"(x));
    return y;
}

// swizzled byte offset inside a [rows]x128-half tile (256B rows, 16B-chunk XOR row&7)
__device__ __forceinline__ uint32_t sw_off(int row, int chunk) {
    return (uint32_t)((row << 8) + ((chunk ^ (row & 7)) << 4));
}

// copy one 64x128 fp16 tile (Q) gmem -> smem, 128 threads
__device__ __forceinline__ void copy_q(uint32_t dst, const __half* src, int tid) {
#pragma unroll
    for (int i = 0; i < 8; i++) {
        int t = tid + i * 128;  // 0..1023
        int row = t >> 4, ch = t & 15;
        cp16(dst + sw_off(row, ch), src + (size_t)row * 2048 + ch * 8);
    }
}
// copy one 32x128 fp16 tile (K or V) gmem -> smem, 128 threads
__device__ __forceinline__ void copy_kv(uint32_t dst, const __half* src, int tid) {
#pragma unroll
    for (int i = 0; i < 4; i++) {
        int t = tid + i * 128;  // 0..511
        int row = t >> 4, ch = t & 15;
        cp16(dst + sw_off(row, ch), src + (size_t)row * 2048 + ch * 8);
    }
}

__global__ __launch_bounds__(THREADS_, 3) void attn_kernel(float* __restrict__ out) {
    extern __shared__ __half smem[];
    uint32_t sbase = (uint32_t)__cvta_generic_to_shared(smem);
    uint32_t sQ = sbase;
    uint32_t sKh[3] = {sbase + QTILE_BYTES,
                       sbase + QTILE_BYTES + 2 * KTILE_BYTES,
                       sbase + QTILE_BYTES + 4 * KTILE_BYTES};
    uint32_t sVh[3] = {sbase + QTILE_BYTES + 1 * KTILE_BYTES,
                       sbase + QTILE_BYTES + 3 * KTILE_BYTES,
                       sbase + QTILE_BYTES + 5 * KTILE_BYTES};

    int bid = blockIdx.x;
    int qt = bid & 15;
    int h = (bid >> 4) & 15;
    int n = (bid >> 8) & 3;
    int b = bid >> 10;

    int tid = threadIdx.x;
    int warp = tid >> 5;
    int lane = tid & 31;
    int q0 = qt * QT_;
    int nktiles = 2 * qt + 2;  // k tiles of 32 rows; last two are the diagonal pair

    const size_t head_off = ((size_t)(b * L_ + n * CHUNK_) * H_ + h) * 128;
    const __half* qsrc  = g_qh + head_off + (size_t)q0 * 2048;
    const __half* khsrc = g_kh + head_off;
    const __half* vhsrc = g_vh + head_off;

    // prologue: {Q, K0, V0} group; {K1, V1} group
    copy_q(sQ, qsrc, tid);
    copy_kv(sKh[0], khsrc, tid);
    copy_kv(sVh[0], vhsrc, tid);
    asm volatile("cp.async.commit_group;\n");
    copy_kv(sKh[1], khsrc + (size_t)KT_ * 2048, tid);
    copy_kv(sVh[1], vhsrc + (size_t)KT_ * 2048, tid);
    asm volatile("cp.async.commit_group;\n");

    float acc[16][4];
#pragma unroll
    for (int i = 0; i < 16; i++)
#pragma unroll
        for (int j2 = 0; j2 < 4; j2++) acc[i][j2] = 0.f;
    float l0 = 0.f, l1 = 0.f;

    // fragment coordinates
    int g = lane >> 3;
    int arow = warp * 16 + (lane & 15);
    int achk = lane >> 4;
    int brow_b = ((g >> 1) << 3) + (lane & 7);
    int bchk = g & 1;
    int vrow_b = ((g & 1) << 3) + (lane & 7);
    int vchk = g >> 1;

    // ============ main loop: kt = 0 .. 2qt-1 (fully unmasked tiles) ============
    for (int kt = 0; kt < 2 * qt; kt++) {
        int cur = kt % 3;
        asm volatile("cp.async.wait_group 1;\n");
        __syncthreads();

        if (kt + 2 < nktiles) {
            int st = (kt + 2) % 3;
            size_t toff = (size_t)(kt + 2) * KT_ * 2048;
            copy_kv(sKh[st], khsrc + toff, tid);
            copy_kv(sVh[st], vhsrc + toff, tid);
            asm volatile("cp.async.commit_group;\n");
        }

        // ---- S = Q K^T (64 q-rows x 32 k-cols per warp slice) ----
        float sacc[4][4];
#pragma unroll
        for (int j = 0; j < 4; j++)
#pragma unroll
            for (int j2 = 0; j2 < 4; j2++) sacc[j][j2] = 0.f;

#pragma unroll
        for (int ks = 0; ks < 8; ks++) {
            uint32_t aH[4];
            ldm_x4(aH, sQ + sw_off(arow, ks * 2 + achk));
#pragma unroll
            for (int jp = 0; jp < 2; jp++) {
                int brow = jp * 16 + brow_b;
                uint32_t bH[4];
                ldm_x4(bH, sKh[cur] + sw_off(brow, ks * 2 + bchk));
                mma16816(sacc[2 * jp],     aH, bH[0], bH[1]);
                mma16816(sacc[2 * jp + 1], aH, bH[2], bH[3]);
            }
        }

        // ---- P = exp2(sacc) ----
        uint32_t pH[4][2];
#pragma unroll
        for (int j = 0; j < 4; j++) {
            float p0 = ex2f(sacc[j][0]);
            float p1 = ex2f(sacc[j][1]);
            float p2 = ex2f(sacc[j][2]);
            float p3 = ex2f(sacc[j][3]);
            l0 += p0 + p1;
            l1 += p2 + p3;
            half2 t0 = __floats2half2_rn(p0, p1);
            half2 t1 = __floats2half2_rn(p2, p3);
            pH[j][0] = *(uint32_t*)&t0;
            pH[j][1] = *(uint32_t*)&t1;
        }

        // ---- O += P V ----
#pragma unroll
        for (int kk = 0; kk < 2; kk++) {
            uint32_t a[4] = {pH[2 * kk][0], pH[2 * kk][1],
                             pH[2 * kk + 1][0], pH[2 * kk + 1][1]};
            int vrow = kk * 16 + vrow_b;
#pragma unroll
            for (int nb = 0; nb < 8; nb++) {
                uint32_t bv[4];
                ldm_x4_t(bv, sVh[cur] + sw_off(vrow, nb * 2 + vchk));
                mma16816(acc[2 * nb],     a, bv[0], bv[1]);
                mma16816(acc[2 * nb + 1], a, bv[2], bv[3]);
            }
        }
    }

    // ============ diagonal pair: tiles 2qt (d=0) and 2qt+1 (d=1) ============
#pragma unroll
    for (int d = 0; d < 2; d++) {
        int kt = 2 * qt + d;
        int cur = kt % 3;
        if (d == 0) {
            asm volatile("cp.async.wait_group 1;\n");
        } else {
            asm volatile("cp.async.wait_group 0;\n");
        }
        __syncthreads();

        if (warp < 2 * d) continue;       // this warp's rows are fully masked
        int bhi = warp - 2 * d;           // live block bound (clamped to 1)
        int jhi = bhi < 1 ? bhi : 1;

        float sacc[4][4];
#pragma unroll
        for (int j = 0; j < 4; j++)
#pragma unroll
            for (int j2 = 0; j2 < 4; j2++) sacc[j][j2] = 0.f;

        for (int jp = 0; jp <= jhi; jp++) {
            int brow = jp * 16 + brow_b;
#pragma unroll
            for (int ks = 0; ks < 8; ks++) {
                uint32_t aH[4];
                ldm_x4(aH, sQ + sw_off(arow, ks * 2 + achk));
                uint32_t bH[4];
                ldm_x4(bH, sKh[cur] + sw_off(brow, ks * 2 + bchk));
                mma16816(sacc[2 * jp],     aH, bH[0], bH[1]);
                mma16816(sacc[2 * jp + 1], aH, bH[2], bH[3]);
            }
        }

        // masked exp: row within q-tile vs col within q-tile (= d*32 + tile col)
        uint32_t pH[4][2];
        int r_lo = warp * 16 + (lane >> 2);
#pragma unroll
        for (int j = 0; j < 4; j++) {
            int c = d * 32 + j * 8 + ((lane & 3) << 1);
            float p0 = (c     <= r_lo)     ? ex2f(sacc[j][0]) : 0.f;
            float p1 = (c + 1 <= r_lo)     ? ex2f(sacc[j][1]) : 0.f;
            float p2 = (c     <= r_lo + 8) ? ex2f(sacc[j][2]) : 0.f;
            float p3 = (c + 1 <= r_lo + 8) ? ex2f(sacc[j][3]) : 0.f;
            l0 += p0 + p1;
            l1 += p2 + p3;
            half2 t0 = __floats2half2_rn(p0, p1);
            half2 t1 = __floats2half2_rn(p2, p3);
            pH[j][0] = *(uint32_t*)&t0;
            pH[j][1] = *(uint32_t*)&t1;
        }

        for (int kk = 0; kk <= jhi; kk++) {
            uint32_t a[4] = {pH[2 * kk][0], pH[2 * kk][1],
                             pH[2 * kk + 1][0], pH[2 * kk + 1][1]};
            int vrow = kk * 16 + vrow_b;
#pragma unroll
            for (int nb = 0; nb < 8; nb++) {
                uint32_t bv[4];
                ldm_x4_t(bv, sVh[cur] + sw_off(vrow, nb * 2 + vchk));
                mma16816(acc[2 * nb],     a, bv[0], bv[1]);
                mma16816(acc[2 * nb + 1], a, bv[2], bv[3]);
            }
        }
    }

    // final row-sum reduce across the quad, then normalize + write
    l0 += __shfl_xor_sync(0xffffffffu, l0, 1);
    l0 += __shfl_xor_sync(0xffffffffu, l0, 2);
    l1 += __shfl_xor_sync(0xffffffffu, l1, 1);
    l1 += __shfl_xor_sync(0xffffffffu, l1, 2);
    float il0 = 1.f / l0, il1 = 1.f / l1;
    int gl0 = n * CHUNK_ + q0 + warp * 16 + (lane >> 2);
    float* o0 = out + ((size_t)(b * L_ + gl0) * H_ + h) * DV_;
    float* o1 = out + ((size_t)(b * L_ + gl0 + 8) * H_ + h) * DV_;
#pragma unroll
    for (int nt = 0; nt < 16; nt++) {
        int c = nt * 8 + ((lane & 3) << 1);
        float2 w0 = make_float2(acc[nt][0] * il0, acc[nt][1] * il0);
        float2 w1 = make_float2(acc[nt][2] * il1, acc[nt][3] * il1);
        *(float2*)(o0 + c) = w0;
        *(float2*)(o1 + c) = w1;
    }
}

extern "C" void kernel_launch(void* const* d_in, const int* in_sizes, int n_in,
                              void* d_out, int out_size) {
    (void)in_sizes; (void)n_in; (void)out_size;
    const float* q = (const float*)d_in[0];
    const float* k = (const float*)d_in[1];
    const float* v = (const float*)d_in[2];
    float* out = (float*)d_out;

    cudaFuncSetAttribute(attn_kernel, cudaFuncAttributeMaxDynamicSharedMemorySize,
                         SMEM_BYTES);
    rope_table_kernel<<<(L_ * 64 + 255) / 256, 256>>>();
    prepass_kernel<<<(B_ * L_ * H_ * 64 + 255) / 256, 256>>>(q, k, v);
    attn_kernel<<<B_ * NCHUNK_ * H_ * 16, THREADS_, SMEM_BYTES>>>(out);
}

// round 16
// speedup vs baseline: 1.0873x; 1.0873x over previous
#include <cuda_runtime.h>
#include <cuda_fp16.h>
#include <cstdint>
#include <math.h>

#define B_ 4
#define L_ 4096
#define H_ 16
#define DH_ 128
#define DV_ 128
#define CHUNK_ 1024
#define NCHUNK_ 4
#define QT_ 64
#define KT_ 64
#define THREADS_ 128
/* (1/sqrt(128)) * log2(e) — folded into Q at prepass; exp(s*scale) == exp2(sacc) */
#define QSCALE_ 0.1275174290f

#define TILE_BYTES_ 16384
#define SMEM_BYTES (7 * TILE_BYTES_) /* Q + 3 stages x (Kh,Vh) = 112KB */

// RoPE cos/sin table: [L_][64] of (cos, sin)
__device__ float2 g_rope[L_ * 64];

// Pre-transformed fp16 tensors, layout [b, l, h, d]
__device__ __half g_qh[B_ * L_ * H_ * DH_];
__device__ __half g_kh[B_ * L_ * H_ * DH_];
__device__ __half g_vh[B_ * L_ * H_ * DV_];

__global__ void rope_table_kernel() {
    int idx = blockIdx.x * blockDim.x + threadIdx.x;
    if (idx >= L_ * 64) return;
    int pos = idx >> 6;
    int j = idx & 63;
    const float coef = -0.14391156831212787f;  // -ln(10000)/64
    float freq = expf((float)j * coef);
    float ang = (float)pos * freq;  // fp32 rounding matches reference
    float s, c;
    sincosf(ang, &s, &c);
    g_rope[idx] = make_float2(c, s);
}

// RoPE + fp16 conversion pre-pass, vectorized: 2 adjacent dims per thread
__global__ void prepass_kernel(const float* __restrict__ q,
                               const float* __restrict__ k,
                               const float* __restrict__ v) {
    int idx = blockIdx.x * blockDim.x + threadIdx.x;
    if (idx >= B_ * L_ * H_ * 32) return;
    int p2 = (idx & 31) * 2;        // 0,2,...,62
    int rh = idx >> 5;              // (b*L + l)*H + h
    int gl = (rh >> 4) & (L_ - 1);  // l  (H_=16)
    size_t base = (size_t)rh * 128;
    float2 cs0 = g_rope[gl * 64 + p2];
    float2 cs1 = g_rope[gl * 64 + p2 + 1];

    float2 xa = *(const float2*)(q + base + p2);
    float2 xb = *(const float2*)(q + base + p2 + 64);
    *(half2*)(g_qh + base + p2) = __floats2half2_rn(
        (xa.x * cs0.x - xb.x * cs0.y) * QSCALE_,
        (xa.y * cs1.x - xb.y * cs1.y) * QSCALE_);
    *(half2*)(g_qh + base + p2 + 64) = __floats2half2_rn(
        (xb.x * cs0.x + xa.x * cs0.y) * QSCALE_,
        (xb.y * cs1.x + xa.y * cs1.y) * QSCALE_);

    xa = *(const float2*)(k + base + p2);
    xb = *(const float2*)(k + base + p2 + 64);
    *(half2*)(g_kh + base + p2) = __floats2half2_rn(
        xa.x * cs0.x - xb.x * cs0.y, xa.y * cs1.x - xb.y * cs1.y);
    *(half2*)(g_kh + base + p2 + 64) = __floats2half2_rn(
        xb.x * cs0.x + xa.x * cs0.y, xb.y * cs1.x + xa.y * cs1.y);

    float2 va = *(const float2*)(v + base + p2);
    float2 vb = *(const float2*)(v + base + p2 + 64);
    *(half2*)(g_vh + base + p2)      = __floats2half2_rn(va.x, va.y);
    *(half2*)(g_vh + base + p2 + 64) = __floats2half2_rn(vb.x, vb.y);
}

__device__ __forceinline__ void ldm_x4(uint32_t r[4], uint32_t a) {
    asm volatile("ldmatrix.sync.aligned.m8n8.x4.shared.b16 {%0,%1,%2,%3}, [%4];\n"
                 : "=r"(r[0]), "=r"(r[1]), "=r"(r[2]), "=r"(r[3]) : "r"(a));
}
__device__ __forceinline__ void ldm_x4_t(uint32_t r[4], uint32_t a) {
    asm volatile("ldmatrix.sync.aligned.m8n8.x4.trans.shared.b16 {%0,%1,%2,%3}, [%4];\n"
                 : "=r"(r[0]), "=r"(r[1]), "=r"(r[2]), "=r"(r[3]) : "r"(a));
}
__device__ __forceinline__ void mma16816(float c[4], const uint32_t a[4],
                                         uint32_t b0, uint32_t b1) {
    asm volatile(
        "mma.sync.aligned.m16n8k16.row.col.f32.f16.f16.f32 "
        "{%0,%1,%2,%3}, {%4,%5,%6,%7}, {%8,%9}, {%0,%1,%2,%3};\n"
        : "+f"(c[0]), "+f"(c[1]), "+f"(c[2]), "+f"(c[3])
        : "r"(a[0]), "r"(a[1]), "r"(a[2]), "r"(a[3]), "r"(b0), "r"(b1));
}
__device__ __forceinline__ void cp16(uint32_t dst, const void* src) {
    asm volatile("cp.async.cg.shared.global [%0], [%1], 16;\n" ::"r"(dst), "l"(src));
}
__device__ __forceinline__ float ex2f(float x) {
    float y;
    asm("ex2.approx.f32 %0, %1;" : "=f"(y) : "f"(x));
    return y;
}

// swizzled byte offset inside a 64x128-half tile (256B rows, 16B-chunk XOR row&7)
__device__ __forceinline__ uint32_t sw_off(int row, int chunk) {
    return (uint32_t)((row << 8) + ((chunk ^ (row & 7)) << 4));
}

// copy one 64x128 fp16 tile gmem -> smem (swizzled), 128 threads
__device__ __forceinline__ void copy_tile(uint32_t dst, const __half* src, int tid) {
#pragma unroll
    for (int i = 0; i < 8; i++) {
        int t = tid + i * 128;  // 0..1023
        int row = t >> 4, ch = t & 15;
        cp16(dst + sw_off(row, ch), src + (size_t)row * 2048 + ch * 8);
    }
}

__global__ __launch_bounds__(THREADS_, 2) void attn_kernel(float* __restrict__ out) {
    extern __shared__ __half smem[];
    uint32_t sbase = (uint32_t)__cvta_generic_to_shared(smem);
    uint32_t sQ = sbase;
    uint32_t sKh[3] = {sbase + 1 * TILE_BYTES_, sbase + 3 * TILE_BYTES_,
                       sbase + 5 * TILE_BYTES_};
    uint32_t sVh[3] = {sbase + 2 * TILE_BYTES_, sbase + 4 * TILE_BYTES_,
                       sbase + 6 * TILE_BYTES_};

    int bid = blockIdx.x;
    int qt = bid & 15;
    int h = (bid >> 4) & 15;
    int n = (bid >> 8) & 3;
    int b = bid >> 10;

    int tid = threadIdx.x;
    int warp = tid >> 5;
    int lane = tid & 31;
    int q0 = qt * QT_;

    const size_t head_off = ((size_t)(b * L_ + n * CHUNK_) * H_ + h) * 128;
    const __half* qsrc  = g_qh + head_off + (size_t)q0 * 2048;
    const __half* khsrc = g_kh + head_off;
    const __half* vhsrc = g_vh + head_off;

    // prologue: Q + tile0 as group; tile1 as second group
    copy_tile(sQ, qsrc, tid);
    copy_tile(sKh[0], khsrc, tid);
    copy_tile(sVh[0], vhsrc, tid);
    asm volatile("cp.async.commit_group;\n");
    if (qt >= 1) {
        copy_tile(sKh[1], khsrc + (size_t)KT_ * 2048, tid);
        copy_tile(sVh[1], vhsrc + (size_t)KT_ * 2048, tid);
        asm volatile("cp.async.commit_group;\n");
    }

    float acc[16][4];
#pragma unroll
    for (int i = 0; i < 16; i++)
#pragma unroll
        for (int j2 = 0; j2 < 4; j2++) acc[i][j2] = 0.f;
    float l0 = 0.f, l1 = 0.f;

    // fragment coordinates
    int g = lane >> 3;
    int arow = warp * 16 + (lane & 15);
    int achk = lane >> 4;
    int brow_b = ((g >> 1) << 3) + (lane & 7);
    int bchk = g & 1;
    int vrow_b = ((g & 1) << 3) + (lane & 7);
    int vchk = g >> 1;

    // hoist Q fragments to registers (once per CTA lifetime)
    asm volatile("cp.async.wait_group 0;\n");
    __syncthreads();
    uint32_t aF[8][4];
#pragma unroll
    for (int ks = 0; ks < 8; ks++)
        ldm_x4(aF[ks], sQ + sw_off(arow, ks * 2 + achk));

    // ================= main loop: kt = 0 .. qt-1 (no diagonal) =================
    for (int kt = 0; kt < qt; kt++) {
        int cur = kt % 3;
        asm volatile("cp.async.wait_group 1;\n");
        __syncthreads();

        if (kt + 2 <= qt) {
            int st = (kt + 2) % 3;
            size_t toff = (size_t)(kt + 2) * KT_ * 2048;
            copy_tile(sKh[st], khsrc + toff, tid);
            copy_tile(sVh[st], vhsrc + toff, tid);
            asm volatile("cp.async.commit_group;\n");
        }

        // ---- S = Q K^T ----
        float sacc[8][4];
#pragma unroll
        for (int j = 0; j < 8; j++)
#pragma unroll
            for (int j2 = 0; j2 < 4; j2++) sacc[j][j2] = 0.f;

#pragma unroll
        for (int ks = 0; ks < 8; ks++) {
#pragma unroll
            for (int jp = 0; jp < 4; jp++) {
                int brow = jp * 16 + brow_b;
                uint32_t bH[4];
                ldm_x4(bH, sKh[cur] + sw_off(brow, ks * 2 + bchk));
                mma16816(sacc[2 * jp],     aF[ks], bH[0], bH[1]);
                mma16816(sacc[2 * jp + 1], aF[ks], bH[2], bH[3]);
            }
        }

        // ---- P = exp2(sacc) (scale*log2e pre-folded into Q) ----
        uint32_t pH[8][2];
#pragma unroll
        for (int j = 0; j < 8; j++) {
            float p0 = ex2f(sacc[j][0]);
            float p1 = ex2f(sacc[j][1]);
            float p2 = ex2f(sacc[j][2]);
            float p3 = ex2f(sacc[j][3]);
            l0 += p0 + p1;
            l1 += p2 + p3;
            half2 t0 = __floats2half2_rn(p0, p1);
            half2 t1 = __floats2half2_rn(p2, p3);
            pH[j][0] = *(uint32_t*)&t0;
            pH[j][1] = *(uint32_t*)&t1;
        }

        // ---- O += P V ----
#pragma unroll
        for (int kk = 0; kk < 4; kk++) {
            uint32_t a[4] = {pH[2 * kk][0], pH[2 * kk][1],
                             pH[2 * kk + 1][0], pH[2 * kk + 1][1]};
            int vrow = kk * 16 + vrow_b;
#pragma unroll
            for (int nb = 0; nb < 8; nb++) {
                uint32_t bv[4];
                ldm_x4_t(bv, sVh[cur] + sw_off(vrow, nb * 2 + vchk));
                mma16816(acc[2 * nb],     a, bv[0], bv[1]);
                mma16816(acc[2 * nb + 1], a, bv[2], bv[3]);
            }
        }
    }

    // ================= diagonal tile (kt == qt): triangular work only =========
    {
        int cur = qt % 3;
        asm volatile("cp.async.wait_group 0;\n");
        __syncthreads();

        float sacc[8][4];
#pragma unroll
        for (int j = 0; j < 8; j++)
#pragma unroll
            for (int j2 = 0; j2 < 4; j2++) sacc[j][j2] = 0.f;

        // QK only for column blocks jp <= warp (rest fully masked anyway)
        for (int jp = 0; jp <= warp; jp++) {
            int brow = jp * 16 + brow_b;
#pragma unroll
            for (int ks = 0; ks < 8; ks++) {
                uint32_t bH[4];
                ldm_x4(bH, sKh[cur] + sw_off(brow, ks * 2 + bchk));
                mma16816(sacc[2 * jp],     aF[ks], bH[0], bH[1]);
                mma16816(sacc[2 * jp + 1], aF[ks], bH[2], bH[3]);
            }
        }

        // masked exp (blocks jp>warp have sacc==0 but mask forces P=0 there)
        uint32_t pH[8][2];
        int r_lo = warp * 16 + (lane >> 2);  // row within Q tile
#pragma unroll
        for (int j = 0; j < 8; j++) {
            int c = j * 8 + ((lane & 3) << 1);  // col within K tile
            float p0 = (c     <= r_lo)     ? ex2f(sacc[j][0]) : 0.f;
            float p1 = (c + 1 <= r_lo)     ? ex2f(sacc[j][1]) : 0.f;
            float p2 = (c     <= r_lo + 8) ? ex2f(sacc[j][2]) : 0.f;
            float p3 = (c + 1 <= r_lo + 8) ? ex2f(sacc[j][3]) : 0.f;
            l0 += p0 + p1;
            l1 += p2 + p3;
            half2 t0 = __floats2half2_rn(p0, p1);
            half2 t1 = __floats2half2_rn(p2, p3);
            pH[j][0] = *(uint32_t*)&t0;
            pH[j][1] = *(uint32_t*)&t1;
        }

        // PV only for row blocks kk <= warp (P is zero beyond)
        for (int kk = 0; kk <= warp; kk++) {
            uint32_t a[4] = {pH[2 * kk][0], pH[2 * kk][1],
                             pH[2 * kk + 1][0], pH[2 * kk + 1][1]};
            int vrow = kk * 16 + vrow_b;
#pragma unroll
            for (int nb = 0; nb < 8; nb++) {
                uint32_t bv[4];
                ldm_x4_t(bv, sVh[cur] + sw_off(vrow, nb * 2 + vchk));
                mma16816(acc[2 * nb],     a, bv[0], bv[1]);
                mma16816(acc[2 * nb + 1], a, bv[2], bv[3]);
            }
        }
    }

    // final row-sum reduce across the quad, then normalize + write
    l0 += __shfl_xor_sync(0xffffffffu, l0, 1);
    l0 += __shfl_xor_sync(0xffffffffu, l0, 2);
    l1 += __shfl_xor_sync(0xffffffffu, l1, 1);
    l1 += __shfl_xor_sync(0xffffffffu, l1, 2);
    float il0 = 1.f / l0, il1 = 1.f / l1;
    int gl0 = n * CHUNK_ + q0 + warp * 16 + (lane >> 2);
    float* o0 = out + ((size_t)(b * L_ + gl0) * H_ + h) * DV_;
    float* o1 = out + ((size_t)(b * L_ + gl0 + 8) * H_ + h) * DV_;
#pragma unroll
    for (int nt = 0; nt < 16; nt++) {
        int c = nt * 8 + ((lane & 3) << 1);
        float2 w0 = make_float2(acc[nt][0] * il0, acc[nt][1] * il0);
        float2 w1 = make_float2(acc[nt][2] * il1, acc[nt][3] * il1);
        *(float2*)(o0 + c) = w0;
        *(float2*)(o1 + c) = w1;
    }
}

extern "C" void kernel_launch(void* const* d_in, const int* in_sizes, int n_in,
                              void* d_out, int out_size) {
    (void)in_sizes; (void)n_in; (void)out_size;
    const float* q = (const float*)d_in[0];
    const float* k = (const float*)d_in[1];
    const float* v = (const float*)d_in[2];
    float* out = (float*)d_out;

    cudaFuncSetAttribute(attn_kernel, cudaFuncAttributeMaxDynamicSharedMemorySize,
                         SMEM_BYTES);
    rope_table_kernel<<<(L_ * 64 + 255) / 256, 256>>>();
    prepass_kernel<<<(B_ * L_ * H_ * 32 + 255) / 256, 256>>>(q, k, v);
    attn_kernel<<<B_ * NCHUNK_ * H_ * 16, THREADS_, SMEM_BYTES>>>(out);
}